// round 5
// baseline (speedup 1.0000x reference)
#include <cuda_runtime.h>
#include <math.h>

#define NN 100000
#define DD 128
#define EE 600000
#define HH 8
#define NB ((NN + 1023) / 1024)   // scan blocks

#define PADA 132
#define PADW 136

// ---------------- scratch (device globals) ------------------------------------
__device__ __align__(16) float g_Q[NN * DD];
__device__ __align__(16) float g_K[NN * DD];
__device__ __align__(16) float g_V[NN * DD];
__device__ __align__(16) float g_Z[NN * DD];   // residual, then +aggr
__device__ __align__(16) float g_scores[EE * HH];   // exp(score)
__device__ float g_ssum[NN * HH];
__device__ __align__(16) float g_eaq[DD];
__device__ __align__(16) float g_eak[DD];
__device__ int g_src[EE];
__device__ int g_dst[EE];
__device__ int g_eid[EE];
__device__ int g_deg[NN];
__device__ int g_off[NN + 1];
__device__ int g_cur[NN];
__device__ int g_bsum[NB];
__device__ int g_boff[NB];
__device__ int g_is64;

// ---------------- helpers ----------------------------------------------------
__device__ __forceinline__ unsigned f2tf(float f) {
    unsigned u;
    asm("cvt.rna.tf32.f32 %0, %1;" : "=r"(u) : "f"(f));
    return u;
}
__device__ __forceinline__ void mma_tf32(float* c, const unsigned* a, const unsigned* b) {
    asm volatile(
        "mma.sync.aligned.m16n8k8.row.col.f32.tf32.tf32.f32 "
        "{%0,%1,%2,%3}, {%4,%5,%6,%7}, {%8,%9}, {%0,%1,%2,%3};"
        : "+f"(c[0]), "+f"(c[1]), "+f"(c[2]), "+f"(c[3])
        : "r"(a[0]), "r"(a[1]), "r"(a[2]), "r"(a[3]), "r"(b[0]), "r"(b[1]));
}
__device__ __forceinline__ void cp16(float* smem_dst, const float* gsrc) {
    unsigned s = (unsigned)__cvta_generic_to_shared(smem_dst);
    asm volatile("cp.async.cg.shared.global [%0], [%1], 16;" :: "r"(s), "l"(gsrc));
}
#define CP_COMMIT() asm volatile("cp.async.commit_group;")
#define CP_WAIT(n)  asm volatile("cp.async.wait_group %0;" :: "n"(n))

// ---------------- dtype detect + deg zero -------------------------------------
__global__ void k_detect(const int* __restrict__ w) {
    int i = blockIdx.x * 256 + threadIdx.x;
    if (i < NN) g_deg[i] = 0;
    if (blockIdx.x == 0) {
        __shared__ int red[256];
        int acc = 0;
        for (int k = threadIdx.x; k < 4096; k += 256) acc |= w[2 * k + 1];
        red[threadIdx.x] = acc;
        __syncthreads();
        for (int s = 128; s > 0; s >>= 1) {
            if (threadIdx.x < s) red[threadIdx.x] |= red[threadIdx.x + s];
            __syncthreads();
        }
        if (threadIdx.x == 0) g_is64 = (red[0] == 0) ? 1 : 0;
    }
}

// ---------------- index conversion + dst histogram -----------------------------
__global__ void k_cvt(const void* __restrict__ ei) {
    int e = blockIdx.x * blockDim.x + threadIdx.x;
    if (e >= EE) return;
    int s, d;
    if (g_is64) {
        const long long* p = (const long long*)ei;
        s = (int)p[e];
        d = (int)p[EE + e];
    } else {
        const int* p = (const int*)ei;
        s = p[e];
        d = p[EE + e];
    }
    g_src[e] = s;
    g_dst[e] = d;
    atomicAdd(&g_deg[d], 1);
}

// ---------------- CSR build: 2-level exclusive scan + scatter ------------------
__global__ void k_scan1() {
    __shared__ int s[1024];
    int t = threadIdx.x;
    int i = blockIdx.x * 1024 + t;
    int v = (i < NN) ? g_deg[i] : 0;
    s[t] = v;
    __syncthreads();
    #pragma unroll
    for (int d = 1; d < 1024; d <<= 1) {
        int x = (t >= d) ? s[t - d] : 0;
        __syncthreads();
        s[t] += x;
        __syncthreads();
    }
    if (i < NN) g_off[i] = s[t] - v;
    if (t == 1023) g_bsum[blockIdx.x] = s[1023];
}
__global__ void k_scan2() {
    if (threadIdx.x == 0) {
        int run = 0;
        for (int b = 0; b < NB; ++b) {
            g_boff[b] = run;
            run += g_bsum[b];
        }
        g_off[NN] = run;
    }
}
__global__ void k_scan3() {
    int i = blockIdx.x * blockDim.x + threadIdx.x;
    if (i < NN) {
        int v = g_off[i] + g_boff[i >> 10];
        g_off[i] = v;
        g_cur[i] = v;
        #pragma unroll
        for (int h = 0; h < HH; ++h) g_ssum[i * HH + h] = 0.f;
    }
}
__global__ void k_scatter() {
    int e = blockIdx.x * blockDim.x + threadIdx.x;
    if (e >= EE) return;
    int pos = atomicAdd(&g_cur[g_dst[e]], 1);
    g_eid[pos] = e;
}

// ---------------- tiny edge-attr MLP (runs once, 1 block) ----------------------
__global__ void k_ea(const float* __restrict__ nt, const float* __restrict__ et,
                     const float* __restrict__ mW1, const float* __restrict__ mb1,
                     const float* __restrict__ m_g, const float* __restrict__ m_b,
                     const float* __restrict__ m_m, const float* __restrict__ m_v,
                     const float* __restrict__ mW2, const float* __restrict__ mb2,
                     const float* __restrict__ qW,  const float* __restrict__ qb,
                     const float* __restrict__ kW,  const float* __restrict__ kb) {
    __shared__ float merged[2 * DD];
    __shared__ float h[DD];
    __shared__ float ea[DD];
    int t = threadIdx.x;  // 128 threads
    merged[t]      = nt[t];
    merged[t + DD] = et[t];
    __syncthreads();
    float s = mb1[t];
    for (int i = 0; i < 2 * DD; ++i) s = fmaf(merged[i], mW1[i * DD + t], s);
    float bn = (s - m_m[t]) * rsqrtf(m_v[t] + 1e-5f) * m_g[t] + m_b[t];
    h[t] = fmaxf(bn, 0.f);
    __syncthreads();
    float s2 = mb2[t];
    for (int i = 0; i < DD; ++i) s2 = fmaf(h[i], mW2[i * DD + t], s2);
    ea[t] = s2;
    __syncthreads();
    float sq = qb[t], sk = kb[t];
    for (int i = 0; i < DD; ++i) {
        sq = fmaf(ea[i], qW[i * DD + t], sq);
        sk = fmaf(ea[i], kW[i * DD + t], sk);
    }
    g_eaq[t] = sq;
    g_eak[t] = sk;
}

// ---------------- node projection GEMM (tf32, cp.async double-buffered W) ------
__global__ __launch_bounds__(256, 1)
void k_proj(const float* __restrict__ x,
            const float* __restrict__ qW, const float* __restrict__ kW,
            const float* __restrict__ vW, const float* __restrict__ resW,
            const float* __restrict__ vb) {
    extern __shared__ float sm[];
    float* As = sm;                       // [128][PADA] (tf32)
    float* Wb[2] = {sm + 128 * PADA, sm + 128 * PADA + 128 * PADW};
    const int t = threadIdx.x;
    const int warp = t >> 5, lane = t & 31;
    const int g = lane >> 2, tg = lane & 3;
    const int wm = warp >> 1, wn = warp & 1;
    const int row0 = blockIdx.x * 128;

    const float* Wg[4] = {qW, kW, vW, resW};
    float*       Og[4] = {g_Q, g_K, g_V, g_Z};

    // prefetch W[0] raw into buffer 0 (async)
    for (int idx = t * 4; idx < 128 * 128; idx += 1024) {
        int r = idx >> 7, c = idx & 127;
        cp16(Wb[0] + r * PADW + c, Wg[0] + idx);
    }
    CP_COMMIT();

    // stage x tile (tf32-rounded)
    for (int idx = t * 4; idx < 128 * 128; idx += 1024) {
        int r = idx >> 7, c = idx & 127;
        int gr = row0 + r;
        float4 v = (gr < NN) ? *(const float4*)(x + (size_t)gr * DD + c)
                             : make_float4(0.f, 0.f, 0.f, 0.f);
        uint4 u = make_uint4(f2tf(v.x), f2tf(v.y), f2tf(v.z), f2tf(v.w));
        *(uint4*)(As + r * PADA + c) = u;
    }
    __syncthreads();

    for (int w = 0; w < 4; ++w) {
        float* Wc = Wb[w & 1];
        float* Wn = Wb[(w + 1) & 1];
        // prefetch next weight while this one computes
        if (w < 3) {
            for (int idx = t * 4; idx < 128 * 128; idx += 1024) {
                int r = idx >> 7, c = idx & 127;
                cp16(Wn + r * PADW + c, Wg[w + 1] + idx);
            }
            CP_COMMIT();
            CP_WAIT(1);   // current weight's copy done (per-thread)
        } else {
            CP_WAIT(0);
        }
        // convert in place (each thread converts exactly what it copied)
        for (int idx = t * 4; idx < 128 * 128; idx += 1024) {
            int r = idx >> 7, c = idx & 127;
            float4 v = *(const float4*)(Wc + r * PADW + c);
            uint4 u = make_uint4(f2tf(v.x), f2tf(v.y), f2tf(v.z), f2tf(v.w));
            *(uint4*)(Wc + r * PADW + c) = u;
        }
        __syncthreads();

        float acc[2][8][4];
        #pragma unroll
        for (int mt = 0; mt < 2; ++mt)
            #pragma unroll
            for (int nt = 0; nt < 8; ++nt)
                #pragma unroll
                for (int j = 0; j < 4; ++j) acc[mt][nt][j] = 0.f;

        const float* Abase = As + (wm * 32 + g) * PADA + tg;
        const float* Bbase = Wc + tg * PADW + wn * 64 + g;

        #pragma unroll 4
        for (int kk = 0; kk < 16; ++kk) {
            unsigned a[2][4], b[8][2];
            #pragma unroll
            for (int mt = 0; mt < 2; ++mt) {
                const float* p = Abase + mt * 16 * PADA + kk * 8;
                a[mt][0] = __float_as_uint(p[0]);
                a[mt][1] = __float_as_uint(p[8 * PADA]);
                a[mt][2] = __float_as_uint(p[4]);
                a[mt][3] = __float_as_uint(p[8 * PADA + 4]);
            }
            #pragma unroll
            for (int nt = 0; nt < 8; ++nt) {
                const float* p = Bbase + kk * 8 * PADW + nt * 8;
                b[nt][0] = __float_as_uint(p[0]);
                b[nt][1] = __float_as_uint(p[4 * PADW]);
            }
            #pragma unroll
            for (int mt = 0; mt < 2; ++mt)
                #pragma unroll
                for (int nt = 0; nt < 8; ++nt)
                    mma_tf32(acc[mt][nt], a[mt], b[nt]);
        }

        float* O = Og[w];
        #pragma unroll
        for (int mt = 0; mt < 2; ++mt) {
            int r = row0 + wm * 32 + mt * 16 + g;
            #pragma unroll
            for (int nt = 0; nt < 8; ++nt) {
                int c = wn * 64 + nt * 8 + tg * 2;
                float bv0 = 0.f, bv1 = 0.f;
                if (w == 0) { bv0 = g_eaq[c]; bv1 = g_eaq[c + 1]; }
                else if (w == 1) { bv0 = g_eak[c]; bv1 = g_eak[c + 1]; }
                else if (w == 2) { bv0 = vb[c]; bv1 = vb[c + 1]; }
                if (r < NN)
                    *(float2*)(O + (size_t)r * DD + c) =
                        make_float2(acc[mt][nt][0] + bv0, acc[mt][nt][1] + bv1);
                if (r + 8 < NN)
                    *(float2*)(O + (size_t)(r + 8) * DD + c) =
                        make_float2(acc[mt][nt][2] + bv0, acc[mt][nt][3] + bv1);
            }
        }
        __syncthreads();   // protect Wn (next buffer) from early prefetch overwrite
    }
}

// ---------------- edge pass: exp(score) + segment sum (warp/edge) --------------
__global__ void k_scores() {
    int gt = blockIdx.x * blockDim.x + threadIdx.x;
    int e = gt >> 5;
    int lane = gt & 31;
    if (e >= EE) return;
    int src = g_src[e];
    int dst = g_dst[e];

    float4 q4 = *(const float4*)(g_Q + (size_t)src * DD + lane * 4);
    float4 k4 = *(const float4*)(g_K + (size_t)dst * DD + lane * 4);
    float p = q4.x * k4.x + q4.y * k4.y + q4.z * k4.z + q4.w * k4.w;
    p += __shfl_xor_sync(0xffffffffu, p, 1);
    p += __shfl_xor_sync(0xffffffffu, p, 2);
    if ((lane & 3) == 0) {
        int h = lane >> 2;
        float ex = expf(p * 0.25f);   // 1/sqrt(DH=16); |s| small -> no max shift
        g_scores[(size_t)e * HH + h] = ex;
        atomicAdd(&g_ssum[src * HH + h], ex);
    }
}

// ---------------- CSR aggregation: one warp per destination node ---------------
__global__ __launch_bounds__(256, 1)
void k_aggr() {
    int n = blockIdx.x * 8 + (threadIdx.x >> 5);
    int lane = threadIdx.x & 31;
    if (n >= NN) return;
    int beg = g_off[n], end = g_off[n + 1];
    int h = lane >> 2;
    float4 acc = *(const float4*)(g_Z + (size_t)n * DD + lane * 4);  // residual
    for (int i = beg; i < end; ++i) {
        int e = g_eid[i];
        int src = g_src[e];
        float ex = g_scores[(size_t)e * HH + h];
        float alpha = ex / g_ssum[src * HH + h];
        float4 v = *(const float4*)(g_V + (size_t)src * DD + lane * 4);
        acc.x = fmaf(v.x, alpha, acc.x);
        acc.y = fmaf(v.y, alpha, acc.y);
        acc.z = fmaf(v.z, alpha, acc.z);
        acc.w = fmaf(v.w, alpha, acc.w);
    }
    *(float4*)(g_Z + (size_t)n * DD + lane * 4) = acc;
}

// ---------------- fused output MLP (tf32) -------------------------------------
__global__ __launch_bounds__(256, 1)
void k_out(const float* __restrict__ oW1, const float* __restrict__ ob1,
           const float* __restrict__ o_g, const float* __restrict__ o_b,
           const float* __restrict__ o_m, const float* __restrict__ o_v,
           const float* __restrict__ oW2, const float* __restrict__ ob2,
           float* __restrict__ out) {
    extern __shared__ float sm[];
    float* As  = sm;                        // [128][PADA]
    float* Ws  = sm + 128 * PADA;           // [128][PADW]
    float* bnS = Ws + 128 * PADW;           // sc[128], sh[128], b1[128]
    const int t = threadIdx.x;
    const int warp = t >> 5, lane = t & 31;
    const int g = lane >> 2, tg = lane & 3;
    const int wm = warp >> 1, wn = warp & 1;
    const int row0 = blockIdx.x * 128;

    for (int idx = t * 4; idx < 128 * 128; idx += 1024) {
        int r = idx >> 7, c = idx & 127;
        int gr = row0 + r;
        float4 v = (gr < NN) ? *(const float4*)(g_Z + (size_t)gr * DD + c)
                             : make_float4(0.f, 0.f, 0.f, 0.f);
        uint4 u = make_uint4(f2tf(v.x), f2tf(v.y), f2tf(v.z), f2tf(v.w));
        *(uint4*)(As + r * PADA + c) = u;
        float4 wv = *(const float4*)(oW1 + idx);
        uint4 wu = make_uint4(f2tf(wv.x), f2tf(wv.y), f2tf(wv.z), f2tf(wv.w));
        *(uint4*)(Ws + r * PADW + c) = wu;
    }
    if (t < 128) {
        float sc = o_g[t] * rsqrtf(o_v[t] + 1e-5f);
        bnS[t]       = sc;
        bnS[128 + t] = o_b[t] - o_m[t] * sc;
        bnS[256 + t] = ob1[t];
    }
    __syncthreads();

    float acc[2][8][4];
    #pragma unroll
    for (int mt = 0; mt < 2; ++mt)
        #pragma unroll
        for (int nt = 0; nt < 8; ++nt)
            #pragma unroll
            for (int j = 0; j < 4; ++j) acc[mt][nt][j] = 0.f;

    const float* Abase = As + (wm * 32 + g) * PADA + tg;
    const float* Bbase = Ws + tg * PADW + wn * 64 + g;

    #pragma unroll 4
    for (int kk = 0; kk < 16; ++kk) {
        unsigned a[2][4], b[8][2];
        #pragma unroll
        for (int mt = 0; mt < 2; ++mt) {
            const float* p = Abase + mt * 16 * PADA + kk * 8;
            a[mt][0] = __float_as_uint(p[0]);
            a[mt][1] = __float_as_uint(p[8 * PADA]);
            a[mt][2] = __float_as_uint(p[4]);
            a[mt][3] = __float_as_uint(p[8 * PADA + 4]);
        }
        #pragma unroll
        for (int nt = 0; nt < 8; ++nt) {
            const float* p = Bbase + kk * 8 * PADW + nt * 8;
            b[nt][0] = __float_as_uint(p[0]);
            b[nt][1] = __float_as_uint(p[4 * PADW]);
        }
        #pragma unroll
        for (int mt = 0; mt < 2; ++mt)
            #pragma unroll
            for (int nt = 0; nt < 8; ++nt)
                mma_tf32(acc[mt][nt], a[mt], b[nt]);
    }
    __syncthreads();

    #pragma unroll
    for (int mt = 0; mt < 2; ++mt) {
        int rl = wm * 32 + mt * 16 + g;
        #pragma unroll
        for (int nt = 0; nt < 8; ++nt) {
            int c = wn * 64 + nt * 8 + tg * 2;
            float sc0 = bnS[c],       sc1 = bnS[c + 1];
            float sh0 = bnS[128 + c], sh1 = bnS[129 + c];
            float b10 = bnS[256 + c], b11 = bnS[257 + c];
            float y0 = (acc[mt][nt][0] + b10) * sc0 + sh0;
            float y1 = (acc[mt][nt][1] + b11) * sc1 + sh1;
            float y2 = (acc[mt][nt][2] + b10) * sc0 + sh0;
            float y3 = (acc[mt][nt][3] + b11) * sc1 + sh1;
            y0 = (y0 > 0.f) ? y0 : 0.01f * y0;
            y1 = (y1 > 0.f) ? y1 : 0.01f * y1;
            y2 = (y2 > 0.f) ? y2 : 0.01f * y2;
            y3 = (y3 > 0.f) ? y3 : 0.01f * y3;
            *(uint2*)(As + rl * PADA + c)       = make_uint2(f2tf(y0), f2tf(y1));
            *(uint2*)(As + (rl + 8) * PADA + c) = make_uint2(f2tf(y2), f2tf(y3));
        }
    }
    for (int idx = t * 4; idx < 128 * 128; idx += 1024) {
        int r = idx >> 7, c = idx & 127;
        float4 wv = *(const float4*)(oW2 + idx);
        uint4 wu = make_uint4(f2tf(wv.x), f2tf(wv.y), f2tf(wv.z), f2tf(wv.w));
        *(uint4*)(Ws + r * PADW + c) = wu;
    }
    __syncthreads();

    #pragma unroll
    for (int mt = 0; mt < 2; ++mt)
        #pragma unroll
        for (int nt = 0; nt < 8; ++nt)
            #pragma unroll
            for (int j = 0; j < 4; ++j) acc[mt][nt][j] = 0.f;

    #pragma unroll 4
    for (int kk = 0; kk < 16; ++kk) {
        unsigned a[2][4], b[8][2];
        #pragma unroll
        for (int mt = 0; mt < 2; ++mt) {
            const float* p = Abase + mt * 16 * PADA + kk * 8;
            a[mt][0] = __float_as_uint(p[0]);
            a[mt][1] = __float_as_uint(p[8 * PADA]);
            a[mt][2] = __float_as_uint(p[4]);
            a[mt][3] = __float_as_uint(p[8 * PADA + 4]);
        }
        #pragma unroll
        for (int nt = 0; nt < 8; ++nt) {
            const float* p = Bbase + kk * 8 * PADW + nt * 8;
            b[nt][0] = __float_as_uint(p[0]);
            b[nt][1] = __float_as_uint(p[4 * PADW]);
        }
        #pragma unroll
        for (int mt = 0; mt < 2; ++mt)
            #pragma unroll
            for (int nt = 0; nt < 8; ++nt)
                mma_tf32(acc[mt][nt], a[mt], b[nt]);
    }

    #pragma unroll
    for (int mt = 0; mt < 2; ++mt) {
        int r = row0 + wm * 32 + mt * 16 + g;
        #pragma unroll
        for (int nt = 0; nt < 8; ++nt) {
            int c = wn * 64 + nt * 8 + tg * 2;
            float b20 = ob2[c], b21 = ob2[c + 1];
            if (r < NN)
                *(float2*)(out + (size_t)r * DD + c) =
                    make_float2(acc[mt][nt][0] + b20, acc[mt][nt][1] + b21);
            if (r + 8 < NN)
                *(float2*)(out + (size_t)(r + 8) * DD + c) =
                    make_float2(acc[mt][nt][2] + b20, acc[mt][nt][3] + b21);
        }
    }
}

// ---------------- launch ------------------------------------------------------
extern "C" void kernel_launch(void* const* d_in, const int* in_sizes, int n_in,
                              void* d_out, int out_size) {
    const float* x    = (const float*)d_in[0];
    const void*  ei   = d_in[1];
    const float* nt   = (const float*)d_in[2];
    const float* et   = (const float*)d_in[3];
    const float* mW1  = (const float*)d_in[4];
    const float* mb1  = (const float*)d_in[5];
    const float* m_g  = (const float*)d_in[6];
    const float* m_b  = (const float*)d_in[7];
    const float* m_m  = (const float*)d_in[8];
    const float* m_v  = (const float*)d_in[9];
    const float* mW2  = (const float*)d_in[10];
    const float* mb2  = (const float*)d_in[11];
    const float* resW = (const float*)d_in[12];
    const float* qW   = (const float*)d_in[13];
    const float* qb   = (const float*)d_in[14];
    const float* kW   = (const float*)d_in[15];
    const float* kb   = (const float*)d_in[16];
    const float* vW   = (const float*)d_in[17];
    const float* vb   = (const float*)d_in[18];
    const float* oW1  = (const float*)d_in[19];
    const float* ob1  = (const float*)d_in[20];
    const float* o_g  = (const float*)d_in[21];
    const float* o_b  = (const float*)d_in[22];
    const float* o_m  = (const float*)d_in[23];
    const float* o_v  = (const float*)d_in[24];
    const float* oW2  = (const float*)d_in[25];
    const float* ob2  = (const float*)d_in[26];
    float* out = (float*)d_out;

    const int SMEM_P = (128 * PADA + 2 * 128 * PADW) * (int)sizeof(float);
    const int SMEM_O = (128 * PADA + 128 * PADW + 3 * 128) * (int)sizeof(float);
    cudaFuncSetAttribute(k_proj, cudaFuncAttributeMaxDynamicSharedMemorySize, SMEM_P);
    cudaFuncSetAttribute(k_out,  cudaFuncAttributeMaxDynamicSharedMemorySize, SMEM_O);

    k_ea<<<1, 128>>>(nt, et, mW1, mb1, m_g, m_b, m_m, m_v, mW2, mb2, qW, qb, kW, kb);
    k_detect<<<(NN + 255) / 256, 256>>>((const int*)ei);
    k_cvt<<<(EE + 255) / 256, 256>>>(ei);
    k_proj<<<(NN + 127) / 128, 256, SMEM_P>>>(x, qW, kW, vW, resW, vb);  // ncu idx 3
    k_scan1<<<NB, 1024>>>();
    k_scan2<<<1, 32>>>();
    k_scan3<<<(NN + 255) / 256, 256>>>();
    k_scatter<<<(EE + 255) / 256, 256>>>();
    k_scores<<<(EE * 32 + 255) / 256, 256>>>();
    k_aggr<<<(NN + 7) / 8, 256>>>();
    k_out<<<(NN + 127) / 128, 256, SMEM_O>>>(oW1, ob1, o_g, o_b, o_m, o_v, oW2, ob2, out);
}

// round 6
// speedup vs baseline: 1.1637x; 1.1637x over previous
#include <cuda_runtime.h>
#include <math.h>

#define NN 100000
#define DD 128
#define EE 600000
#define HH 8
#define NB ((NN + 1023) / 1024)   // scan blocks

#define PADA 132
#define PADW 136

// ---------------- scratch (device globals) ------------------------------------
__device__ __align__(16) float g_Q[NN * DD];
__device__ __align__(16) float g_K[NN * DD];
__device__ __align__(16) float g_V[NN * DD];
__device__ __align__(16) float g_Z[NN * DD];   // residual, then +aggr
__device__ __align__(16) float g_scores[EE * HH];   // exp(score)
__device__ float g_ssum[NN * HH];
__device__ __align__(16) float g_eaq[DD];
__device__ __align__(16) float g_eak[DD];
__device__ int g_src[EE];
__device__ int g_dst[EE];
__device__ int g_eid[EE];
__device__ int g_deg[NN];
__device__ int g_off[NN + 1];
__device__ int g_cur[NN];
__device__ int g_bsum[NB];
__device__ int g_boff[NB];
__device__ int g_is64;

// ---------------- helpers ----------------------------------------------------
__device__ __forceinline__ unsigned f2tf(float f) {
    unsigned u;
    asm("cvt.rna.tf32.f32 %0, %1;" : "=r"(u) : "f"(f));
    return u;
}
__device__ __forceinline__ void mma_tf32(float* c, const unsigned* a, const unsigned* b) {
    asm volatile(
        "mma.sync.aligned.m16n8k8.row.col.f32.tf32.tf32.f32 "
        "{%0,%1,%2,%3}, {%4,%5,%6,%7}, {%8,%9}, {%0,%1,%2,%3};"
        : "+f"(c[0]), "+f"(c[1]), "+f"(c[2]), "+f"(c[3])
        : "r"(a[0]), "r"(a[1]), "r"(a[2]), "r"(a[3]), "r"(b[0]), "r"(b[1]));
}
__device__ __forceinline__ void cp16(float* smem_dst, const float* gsrc) {
    unsigned s = (unsigned)__cvta_generic_to_shared(smem_dst);
    asm volatile("cp.async.cg.shared.global [%0], [%1], 16;" :: "r"(s), "l"(gsrc));
}
#define CP_COMMIT() asm volatile("cp.async.commit_group;")
#define CP_WAIT(n)  asm volatile("cp.async.wait_group %0;" :: "n"(n))

// ---------------- dtype detect + deg zero -------------------------------------
__global__ void k_detect(const int* __restrict__ w) {
    int i = blockIdx.x * 256 + threadIdx.x;
    if (i < NN) g_deg[i] = 0;
    if (blockIdx.x == 0) {
        __shared__ int red[256];
        int acc = 0;
        for (int k = threadIdx.x; k < 4096; k += 256) acc |= w[2 * k + 1];
        red[threadIdx.x] = acc;
        __syncthreads();
        for (int s = 128; s > 0; s >>= 1) {
            if (threadIdx.x < s) red[threadIdx.x] |= red[threadIdx.x + s];
            __syncthreads();
        }
        if (threadIdx.x == 0) g_is64 = (red[0] == 0) ? 1 : 0;
    }
}

// ---------------- index conversion + dst histogram -----------------------------
__global__ void k_cvt(const void* __restrict__ ei) {
    int e = blockIdx.x * blockDim.x + threadIdx.x;
    if (e >= EE) return;
    int s, d;
    if (g_is64) {
        const long long* p = (const long long*)ei;
        s = (int)p[e];
        d = (int)p[EE + e];
    } else {
        const int* p = (const int*)ei;
        s = p[e];
        d = p[EE + e];
    }
    g_src[e] = s;
    g_dst[e] = d;
    atomicAdd(&g_deg[d], 1);
}

// ---------------- CSR build: 2-level exclusive scan + scatter ------------------
__global__ void k_scan1() {
    __shared__ int s[1024];
    int t = threadIdx.x;
    int i = blockIdx.x * 1024 + t;
    int v = (i < NN) ? g_deg[i] : 0;
    s[t] = v;
    __syncthreads();
    #pragma unroll
    for (int d = 1; d < 1024; d <<= 1) {
        int x = (t >= d) ? s[t - d] : 0;
        __syncthreads();
        s[t] += x;
        __syncthreads();
    }
    if (i < NN) g_off[i] = s[t] - v;
    if (t == 1023) g_bsum[blockIdx.x] = s[1023];
}
__global__ void k_scan2() {
    if (threadIdx.x == 0) {
        int run = 0;
        for (int b = 0; b < NB; ++b) {
            g_boff[b] = run;
            run += g_bsum[b];
        }
        g_off[NN] = run;
    }
}
__global__ void k_scan3() {
    int i = blockIdx.x * blockDim.x + threadIdx.x;
    if (i < NN) {
        int v = g_off[i] + g_boff[i >> 10];
        g_off[i] = v;
        g_cur[i] = v;
        #pragma unroll
        for (int h = 0; h < HH; ++h) g_ssum[i * HH + h] = 0.f;
    }
}
__global__ void k_scatter() {
    int e = blockIdx.x * blockDim.x + threadIdx.x;
    if (e >= EE) return;
    int pos = atomicAdd(&g_cur[g_dst[e]], 1);
    g_eid[pos] = e;
}

// ---------------- tiny edge-attr MLP (runs once, 1 block) ----------------------
__global__ void k_ea(const float* __restrict__ nt, const float* __restrict__ et,
                     const float* __restrict__ mW1, const float* __restrict__ mb1,
                     const float* __restrict__ m_g, const float* __restrict__ m_b,
                     const float* __restrict__ m_m, const float* __restrict__ m_v,
                     const float* __restrict__ mW2, const float* __restrict__ mb2,
                     const float* __restrict__ qW,  const float* __restrict__ qb,
                     const float* __restrict__ kW,  const float* __restrict__ kb) {
    __shared__ float merged[2 * DD];
    __shared__ float h[DD];
    __shared__ float ea[DD];
    int t = threadIdx.x;  // 128 threads
    merged[t]      = nt[t];
    merged[t + DD] = et[t];
    __syncthreads();
    float s = mb1[t];
    for (int i = 0; i < 2 * DD; ++i) s = fmaf(merged[i], mW1[i * DD + t], s);
    float bn = (s - m_m[t]) * rsqrtf(m_v[t] + 1e-5f) * m_g[t] + m_b[t];
    h[t] = fmaxf(bn, 0.f);
    __syncthreads();
    float s2 = mb2[t];
    for (int i = 0; i < DD; ++i) s2 = fmaf(h[i], mW2[i * DD + t], s2);
    ea[t] = s2;
    __syncthreads();
    float sq = qb[t], sk = kb[t];
    for (int i = 0; i < DD; ++i) {
        sq = fmaf(ea[i], qW[i * DD + t], sq);
        sk = fmaf(ea[i], kW[i * DD + t], sk);
    }
    g_eaq[t] = sq;
    g_eak[t] = sk;
}

// ---------------- node projection GEMM (tf32, 512 thr, 16 warps 4Mx4N) ---------
__global__ __launch_bounds__(512, 1)
void k_proj(const float* __restrict__ x,
            const float* __restrict__ qW, const float* __restrict__ kW,
            const float* __restrict__ vW, const float* __restrict__ resW,
            const float* __restrict__ vb) {
    extern __shared__ float sm[];
    float* As = sm;                       // [128][PADA] (tf32)
    float* Wb[2] = {sm + 128 * PADA, sm + 128 * PADA + 128 * PADW};
    const int t = threadIdx.x;
    const int warp = t >> 5, lane = t & 31;
    const int g = lane >> 2, tg = lane & 3;
    const int wm = warp >> 2, wn = warp & 3;   // 4x4 warp grid, tile 32x32
    const int row0 = blockIdx.x * 128;

    const float* Wg[4] = {qW, kW, vW, resW};
    float*       Og[4] = {g_Q, g_K, g_V, g_Z};

    // prefetch W[0] raw into buffer 0 (async)
    for (int idx = t * 4; idx < 128 * 128; idx += 2048) {
        int r = idx >> 7, c = idx & 127;
        cp16(Wb[0] + r * PADW + c, Wg[0] + idx);
    }
    CP_COMMIT();

    // stage x tile (tf32-rounded)
    for (int idx = t * 4; idx < 128 * 128; idx += 2048) {
        int r = idx >> 7, c = idx & 127;
        int gr = row0 + r;
        float4 v = (gr < NN) ? *(const float4*)(x + (size_t)gr * DD + c)
                             : make_float4(0.f, 0.f, 0.f, 0.f);
        uint4 u = make_uint4(f2tf(v.x), f2tf(v.y), f2tf(v.z), f2tf(v.w));
        *(uint4*)(As + r * PADA + c) = u;
    }
    __syncthreads();

    for (int w = 0; w < 4; ++w) {
        float* Wc = Wb[w & 1];
        float* Wn = Wb[(w + 1) & 1];
        if (w < 3) {
            for (int idx = t * 4; idx < 128 * 128; idx += 2048) {
                int r = idx >> 7, c = idx & 127;
                cp16(Wn + r * PADW + c, Wg[w + 1] + idx);
            }
            CP_COMMIT();
            CP_WAIT(1);
        } else {
            CP_WAIT(0);
        }
        // convert in place (each thread converts exactly what it copied)
        for (int idx = t * 4; idx < 128 * 128; idx += 2048) {
            int r = idx >> 7, c = idx & 127;
            float4 v = *(const float4*)(Wc + r * PADW + c);
            uint4 u = make_uint4(f2tf(v.x), f2tf(v.y), f2tf(v.z), f2tf(v.w));
            *(uint4*)(Wc + r * PADW + c) = u;
        }
        __syncthreads();

        float acc[2][4][4];
        #pragma unroll
        for (int mt = 0; mt < 2; ++mt)
            #pragma unroll
            for (int nt = 0; nt < 4; ++nt)
                #pragma unroll
                for (int j = 0; j < 4; ++j) acc[mt][nt][j] = 0.f;

        const float* Abase = As + (wm * 32 + g) * PADA + tg;
        const float* Bbase = Wc + tg * PADW + wn * 32 + g;

        #pragma unroll 4
        for (int kk = 0; kk < 16; ++kk) {
            unsigned a[2][4], b[4][2];
            #pragma unroll
            for (int mt = 0; mt < 2; ++mt) {
                const float* p = Abase + mt * 16 * PADA + kk * 8;
                a[mt][0] = __float_as_uint(p[0]);
                a[mt][1] = __float_as_uint(p[8 * PADA]);
                a[mt][2] = __float_as_uint(p[4]);
                a[mt][3] = __float_as_uint(p[8 * PADA + 4]);
            }
            #pragma unroll
            for (int nt = 0; nt < 4; ++nt) {
                const float* p = Bbase + kk * 8 * PADW + nt * 8;
                b[nt][0] = __float_as_uint(p[0]);
                b[nt][1] = __float_as_uint(p[4 * PADW]);
            }
            #pragma unroll
            for (int mt = 0; mt < 2; ++mt)
                #pragma unroll
                for (int nt = 0; nt < 4; ++nt)
                    mma_tf32(acc[mt][nt], a[mt], b[nt]);
        }

        float* O = Og[w];
        #pragma unroll
        for (int mt = 0; mt < 2; ++mt) {
            int r = row0 + wm * 32 + mt * 16 + g;
            #pragma unroll
            for (int nt = 0; nt < 4; ++nt) {
                int c = wn * 32 + nt * 8 + tg * 2;
                float bv0 = 0.f, bv1 = 0.f;
                if (w == 0) { bv0 = g_eaq[c]; bv1 = g_eaq[c + 1]; }
                else if (w == 1) { bv0 = g_eak[c]; bv1 = g_eak[c + 1]; }
                else if (w == 2) { bv0 = vb[c]; bv1 = vb[c + 1]; }
                if (r < NN)
                    *(float2*)(O + (size_t)r * DD + c) =
                        make_float2(acc[mt][nt][0] + bv0, acc[mt][nt][1] + bv1);
                if (r + 8 < NN)
                    *(float2*)(O + (size_t)(r + 8) * DD + c) =
                        make_float2(acc[mt][nt][2] + bv0, acc[mt][nt][3] + bv1);
            }
        }
        __syncthreads();   // protect next buffer from early prefetch overwrite
    }
}

// ---------------- edge pass: exp(score) + segment sum (warp/edge) --------------
__global__ void k_scores() {
    int gt = blockIdx.x * blockDim.x + threadIdx.x;
    int e = gt >> 5;
    int lane = gt & 31;
    if (e >= EE) return;
    int src = g_src[e];
    int dst = g_dst[e];

    float4 q4 = *(const float4*)(g_Q + (size_t)src * DD + lane * 4);
    float4 k4 = *(const float4*)(g_K + (size_t)dst * DD + lane * 4);
    float p = q4.x * k4.x + q4.y * k4.y + q4.z * k4.z + q4.w * k4.w;
    p += __shfl_xor_sync(0xffffffffu, p, 1);
    p += __shfl_xor_sync(0xffffffffu, p, 2);
    if ((lane & 3) == 0) {
        int h = lane >> 2;
        float ex = expf(p * 0.25f);   // 1/sqrt(DH=16); |s| small -> no max shift
        g_scores[(size_t)e * HH + h] = ex;
        atomicAdd(&g_ssum[src * HH + h], ex);
    }
}

// ---------------- CSR aggregation: one warp per destination node ---------------
__global__ __launch_bounds__(256, 1)
void k_aggr() {
    int n = blockIdx.x * 8 + (threadIdx.x >> 5);
    int lane = threadIdx.x & 31;
    if (n >= NN) return;
    int beg = g_off[n], end = g_off[n + 1];
    int h = lane >> 2;
    float4 acc = *(const float4*)(g_Z + (size_t)n * DD + lane * 4);  // residual
    for (int i = beg; i < end; ++i) {
        int e = g_eid[i];
        int src = g_src[e];
        float ex = g_scores[(size_t)e * HH + h];
        float alpha = ex / g_ssum[src * HH + h];
        float4 v = *(const float4*)(g_V + (size_t)src * DD + lane * 4);
        acc.x = fmaf(v.x, alpha, acc.x);
        acc.y = fmaf(v.y, alpha, acc.y);
        acc.z = fmaf(v.z, alpha, acc.z);
        acc.w = fmaf(v.w, alpha, acc.w);
    }
    *(float4*)(g_Z + (size_t)n * DD + lane * 4) = acc;
}

// ---------------- fused output MLP (tf32, 512 thr, 16 warps 4Mx4N) -------------
__global__ __launch_bounds__(512, 1)
void k_out(const float* __restrict__ oW1, const float* __restrict__ ob1,
           const float* __restrict__ o_g, const float* __restrict__ o_b,
           const float* __restrict__ o_m, const float* __restrict__ o_v,
           const float* __restrict__ oW2, const float* __restrict__ ob2,
           float* __restrict__ out) {
    extern __shared__ float sm[];
    float* As  = sm;                        // [128][PADA]
    float* Ws  = sm + 128 * PADA;           // [128][PADW]
    float* bnS = Ws + 128 * PADW;           // sc[128], sh[128], b1[128]
    const int t = threadIdx.x;
    const int warp = t >> 5, lane = t & 31;
    const int g = lane >> 2, tg = lane & 3;
    const int wm = warp >> 2, wn = warp & 3;
    const int row0 = blockIdx.x * 128;

    for (int idx = t * 4; idx < 128 * 128; idx += 2048) {
        int r = idx >> 7, c = idx & 127;
        int gr = row0 + r;
        float4 v = (gr < NN) ? *(const float4*)(g_Z + (size_t)gr * DD + c)
                             : make_float4(0.f, 0.f, 0.f, 0.f);
        uint4 u = make_uint4(f2tf(v.x), f2tf(v.y), f2tf(v.z), f2tf(v.w));
        *(uint4*)(As + r * PADA + c) = u;
        float4 wv = *(const float4*)(oW1 + idx);
        uint4 wu = make_uint4(f2tf(wv.x), f2tf(wv.y), f2tf(wv.z), f2tf(wv.w));
        *(uint4*)(Ws + r * PADW + c) = wu;
    }
    if (t < 128) {
        float sc = o_g[t] * rsqrtf(o_v[t] + 1e-5f);
        bnS[t]       = sc;
        bnS[128 + t] = o_b[t] - o_m[t] * sc;
        bnS[256 + t] = ob1[t];
    }
    __syncthreads();

    float acc[2][4][4];
    #pragma unroll
    for (int mt = 0; mt < 2; ++mt)
        #pragma unroll
        for (int nt = 0; nt < 4; ++nt)
            #pragma unroll
            for (int j = 0; j < 4; ++j) acc[mt][nt][j] = 0.f;

    const float* Abase = As + (wm * 32 + g) * PADA + tg;
    const float* Bbase = Ws + tg * PADW + wn * 32 + g;

    #pragma unroll 4
    for (int kk = 0; kk < 16; ++kk) {
        unsigned a[2][4], b[4][2];
        #pragma unroll
        for (int mt = 0; mt < 2; ++mt) {
            const float* p = Abase + mt * 16 * PADA + kk * 8;
            a[mt][0] = __float_as_uint(p[0]);
            a[mt][1] = __float_as_uint(p[8 * PADA]);
            a[mt][2] = __float_as_uint(p[4]);
            a[mt][3] = __float_as_uint(p[8 * PADA + 4]);
        }
        #pragma unroll
        for (int nt = 0; nt < 4; ++nt) {
            const float* p = Bbase + kk * 8 * PADW + nt * 8;
            b[nt][0] = __float_as_uint(p[0]);
            b[nt][1] = __float_as_uint(p[4 * PADW]);
        }
        #pragma unroll
        for (int mt = 0; mt < 2; ++mt)
            #pragma unroll
            for (int nt = 0; nt < 4; ++nt)
                mma_tf32(acc[mt][nt], a[mt], b[nt]);
    }
    __syncthreads();

    // BN + leakyReLU on fragments, re-stage Y (tf32) into As
    #pragma unroll
    for (int mt = 0; mt < 2; ++mt) {
        int rl = wm * 32 + mt * 16 + g;
        #pragma unroll
        for (int nt = 0; nt < 4; ++nt) {
            int c = wn * 32 + nt * 8 + tg * 2;
            float sc0 = bnS[c],       sc1 = bnS[c + 1];
            float sh0 = bnS[128 + c], sh1 = bnS[129 + c];
            float b10 = bnS[256 + c], b11 = bnS[257 + c];
            float y0 = (acc[mt][nt][0] + b10) * sc0 + sh0;
            float y1 = (acc[mt][nt][1] + b11) * sc1 + sh1;
            float y2 = (acc[mt][nt][2] + b10) * sc0 + sh0;
            float y3 = (acc[mt][nt][3] + b11) * sc1 + sh1;
            y0 = (y0 > 0.f) ? y0 : 0.01f * y0;
            y1 = (y1 > 0.f) ? y1 : 0.01f * y1;
            y2 = (y2 > 0.f) ? y2 : 0.01f * y2;
            y3 = (y3 > 0.f) ? y3 : 0.01f * y3;
            *(uint2*)(As + rl * PADA + c)       = make_uint2(f2tf(y0), f2tf(y1));
            *(uint2*)(As + (rl + 8) * PADA + c) = make_uint2(f2tf(y2), f2tf(y3));
        }
    }
    for (int idx = t * 4; idx < 128 * 128; idx += 2048) {
        int r = idx >> 7, c = idx & 127;
        float4 wv = *(const float4*)(oW2 + idx);
        uint4 wu = make_uint4(f2tf(wv.x), f2tf(wv.y), f2tf(wv.z), f2tf(wv.w));
        *(uint4*)(Ws + r * PADW + c) = wu;
    }
    __syncthreads();

    #pragma unroll
    for (int mt = 0; mt < 2; ++mt)
        #pragma unroll
        for (int nt = 0; nt < 4; ++nt)
            #pragma unroll
            for (int j = 0; j < 4; ++j) acc[mt][nt][j] = 0.f;

    #pragma unroll 4
    for (int kk = 0; kk < 16; ++kk) {
        unsigned a[2][4], b[4][2];
        #pragma unroll
        for (int mt = 0; mt < 2; ++mt) {
            const float* p = Abase + mt * 16 * PADA + kk * 8;
            a[mt][0] = __float_as_uint(p[0]);
            a[mt][1] = __float_as_uint(p[8 * PADA]);
            a[mt][2] = __float_as_uint(p[4]);
            a[mt][3] = __float_as_uint(p[8 * PADA + 4]);
        }
        #pragma unroll
        for (int nt = 0; nt < 4; ++nt) {
            const float* p = Bbase + kk * 8 * PADW + nt * 8;
            b[nt][0] = __float_as_uint(p[0]);
            b[nt][1] = __float_as_uint(p[4 * PADW]);
        }
        #pragma unroll
        for (int mt = 0; mt < 2; ++mt)
            #pragma unroll
            for (int nt = 0; nt < 4; ++nt)
                mma_tf32(acc[mt][nt], a[mt], b[nt]);
    }

    #pragma unroll
    for (int mt = 0; mt < 2; ++mt) {
        int r = row0 + wm * 32 + mt * 16 + g;
        #pragma unroll
        for (int nt = 0; nt < 4; ++nt) {
            int c = wn * 32 + nt * 8 + tg * 2;
            float b20 = ob2[c], b21 = ob2[c + 1];
            if (r < NN)
                *(float2*)(out + (size_t)r * DD + c) =
                    make_float2(acc[mt][nt][0] + b20, acc[mt][nt][1] + b21);
            if (r + 8 < NN)
                *(float2*)(out + (size_t)(r + 8) * DD + c) =
                    make_float2(acc[mt][nt][2] + b20, acc[mt][nt][3] + b21);
        }
    }
}

// ---------------- launch ------------------------------------------------------
extern "C" void kernel_launch(void* const* d_in, const int* in_sizes, int n_in,
                              void* d_out, int out_size) {
    const float* x    = (const float*)d_in[0];
    const void*  ei   = d_in[1];
    const float* nt   = (const float*)d_in[2];
    const float* et   = (const float*)d_in[3];
    const float* mW1  = (const float*)d_in[4];
    const float* mb1  = (const float*)d_in[5];
    const float* m_g  = (const float*)d_in[6];
    const float* m_b  = (const float*)d_in[7];
    const float* m_m  = (const float*)d_in[8];
    const float* m_v  = (const float*)d_in[9];
    const float* mW2  = (const float*)d_in[10];
    const float* mb2  = (const float*)d_in[11];
    const float* resW = (const float*)d_in[12];
    const float* qW   = (const float*)d_in[13];
    const float* qb   = (const float*)d_in[14];
    const float* kW   = (const float*)d_in[15];
    const float* kb   = (const float*)d_in[16];
    const float* vW   = (const float*)d_in[17];
    const float* vb   = (const float*)d_in[18];
    const float* oW1  = (const float*)d_in[19];
    const float* ob1  = (const float*)d_in[20];
    const float* o_g  = (const float*)d_in[21];
    const float* o_b  = (const float*)d_in[22];
    const float* o_m  = (const float*)d_in[23];
    const float* o_v  = (const float*)d_in[24];
    const float* oW2  = (const float*)d_in[25];
    const float* ob2  = (const float*)d_in[26];
    float* out = (float*)d_out;

    const int SMEM_P = (128 * PADA + 2 * 128 * PADW) * (int)sizeof(float);
    const int SMEM_O = (128 * PADA + 128 * PADW + 3 * 128) * (int)sizeof(float);
    cudaFuncSetAttribute(k_proj, cudaFuncAttributeMaxDynamicSharedMemorySize, SMEM_P);
    cudaFuncSetAttribute(k_out,  cudaFuncAttributeMaxDynamicSharedMemorySize, SMEM_O);

    k_ea<<<1, 128>>>(nt, et, mW1, mb1, m_g, m_b, m_m, m_v, mW2, mb2, qW, qb, kW, kb);
    k_detect<<<(NN + 255) / 256, 256>>>((const int*)ei);
    k_cvt<<<(EE + 255) / 256, 256>>>(ei);
    k_proj<<<(NN + 127) / 128, 512, SMEM_P>>>(x, qW, kW, vW, resW, vb);  // ncu idx 3
    k_scan1<<<NB, 1024>>>();
    k_scan2<<<1, 32>>>();
    k_scan3<<<(NN + 255) / 256, 256>>>();
    k_scatter<<<(EE + 255) / 256, 256>>>();
    k_scores<<<(EE * 32 + 255) / 256, 256>>>();
    k_aggr<<<(NN + 7) / 8, 256>>>();
    k_out<<<(NN + 127) / 128, 512, SMEM_O>>>(oW1, ob1, o_g, o_b, o_m, o_v, oW2, ob2, out);
}